// round 10
// baseline (speedup 1.0000x reference)
#include <cuda_runtime.h>
#include <cuda_bf16.h>
#include <math.h>
#include <stdint.h>

#define NPIX 65536

// ---------- static scratch ----------
__device__ float g_grid[NPIX * 32];
__device__ float g_h2f[33554432];                          // [65536,512] fp32 partial
__device__ __align__(16) __nv_bfloat16 g_midh[67108864];   // [65536,1024]
__device__ __align__(16) __nv_bfloat16 g_midl[67108864];
__device__ __align__(16) __nv_bfloat16 g_h2bh[33554432];   // [65536,512]
__device__ __align__(16) __nv_bfloat16 g_h2bl[33554432];
__device__ __align__(16) __nv_bfloat16 g_wf1h[2097152], g_wf1l[2097152];
__device__ __align__(16) __nv_bfloat16 g_wg1h[2097152], g_wg1l[2097152];
__device__ __align__(16) __nv_bfloat16 g_wf2h[524288],  g_wf2l[524288];
__device__ __align__(16) __nv_bfloat16 g_wg2h[524288],  g_wg2l[524288];
__device__ __align__(16) __nv_bfloat16 g_w2mh[524288],  g_w2ml[524288];
__device__ float g_convA[768 * 64];
__device__ float g_convB[768 * 64];
__device__ float g_feat[2048];
__device__ float g_c1v[1024];

__device__ __forceinline__ float lrelu(float x) { return x > 0.f ? x : 0.01f * x; }
__device__ __forceinline__ void bf_split(float v, unsigned short& h, unsigned short& l) {
    __nv_bfloat16 hb = __float2bfloat16(v);
    l = __bfloat16_as_ushort(__float2bfloat16(v - __bfloat162float(hb)));
    h = __bfloat16_as_ushort(hb);
}

// ---------- PTX helpers (baseline sm_80 features only) ----------
__device__ __forceinline__ uint32_t smem_u32(const void* p) {
    uint32_t a;
    asm("{ .reg .u64 t; cvta.to.shared.u64 t, %1; cvt.u32.u64 %0, t; }" : "=r"(a) : "l"(p));
    return a;
}
__device__ __forceinline__ void cpa(uint32_t dst, const void* src) {
    asm volatile("cp.async.ca.shared.global [%0], [%1], 16;" :: "r"(dst), "l"(src));
}
#define CP_COMMIT() asm volatile("cp.async.commit_group;" ::: "memory")
template <int N> __device__ __forceinline__ void cp_wait() {
    asm volatile("cp.async.wait_group %0;" :: "n"(N) : "memory");
}
__device__ __forceinline__ void ldmx4(uint32_t* r, uint32_t addr) {
    asm volatile("ldmatrix.sync.aligned.m8n8.x4.shared.b16 {%0,%1,%2,%3}, [%4];"
        : "=r"(r[0]), "=r"(r[1]), "=r"(r[2]), "=r"(r[3]) : "r"(addr));
}
__device__ __forceinline__ void mma16816(float* d, const uint32_t* a, const uint32_t* b) {
    asm volatile(
        "mma.sync.aligned.m16n8k16.row.col.f32.bf16.bf16.f32 "
        "{%0,%1,%2,%3}, {%4,%5,%6,%7}, {%8,%9}, {%0,%1,%2,%3};"
        : "+f"(d[0]), "+f"(d[1]), "+f"(d[2]), "+f"(d[3])
        : "r"(a[0]), "r"(a[1]), "r"(a[2]), "r"(a[3]), "r"(b[0]), "r"(b[1]));
}

// ---------- grid features ----------
__global__ void k_gridgen(float* __restrict__ g) {
    int p = blockIdx.x * blockDim.x + threadIdx.x;
    float fi = (float)((p >> 8) - 128);
    float fj = (float)((p & 255) - 128);
    float* row = g + (size_t)p * 32;
#pragma unroll
    for (int k = 0; k < 16; k++) {
        float s = exp2f(0.5f * k - 8.0f);
        row[2 * k]     = sinpif(fi * s);
        row[2 * k + 1] = sinpif(fj * s);
    }
}

// ---------- 3x3 grouped conv, 256 thr, 4-way ci slices ----------
__global__ void k_conv(const float* __restrict__ in, const float* __restrict__ w,
                       const float* __restrict__ b, float* __restrict__ out,
                       int Cipg, int Cout, int Hin, int Win, int Hout, int Wout,
                       int pad, int groups) {
    extern __shared__ float ws[];
    __shared__ float red[4][64];
    int o = blockIdx.x;
    int opg = Cout / groups;
    const float* inb = in + (size_t)(o / opg) * Cipg * Hin * Win;
    const float* wb = w + (size_t)o * Cipg * 9;
    int nw = Cipg * 9;
    for (int i = threadIdx.x; i < nw; i += blockDim.x) ws[i] = wb[i];
    __syncthreads();
    int np = Hout * Wout;
    int sl = threadIdx.x >> 6, p = threadIdx.x & 63;
    int cps = Cipg >> 2;
    float acc = 0.f;
    if (p < np) {
        int y = p / Wout, x = p % Wout;
        for (int ci = sl * cps; ci < (sl + 1) * cps; ci++) {
            const float* ip = inb + (size_t)ci * Hin * Win;
            const float* wp = ws + ci * 9;
#pragma unroll
            for (int ky = 0; ky < 3; ky++) {
                int iy = y + ky - pad;
                if ((unsigned)iy < (unsigned)Hin) {
#pragma unroll
                    for (int kx = 0; kx < 3; kx++) {
                        int ix = x + kx - pad;
                        if ((unsigned)ix < (unsigned)Win)
                            acc += ip[iy * Win + ix] * wp[ky * 3 + kx];
                    }
                }
            }
        }
    }
    red[sl][p] = acc;
    __syncthreads();
    if (sl == 0 && p < np)
        out[(size_t)o * np + p] = lrelu(red[0][p] + red[1][p] + red[2][p] + red[3][p] + b[o]);
}

// ---------- weight norm + bf16 split ----------
__global__ void k_wnorm_s(const float* __restrict__ v, const float* __restrict__ g,
                          __nv_bfloat16* __restrict__ oh, __nv_bfloat16* __restrict__ ol, int R) {
    int row = blockIdx.x;
    const float* vr = v + (size_t)row * R;
    float s = 0.f;
    for (int k = threadIdx.x; k < R; k += 256) { float x = vr[k]; s += x * x; }
    __shared__ float red[256];
    red[threadIdx.x] = s;
    __syncthreads();
    for (int st = 128; st > 0; st >>= 1) {
        if (threadIdx.x < st) red[threadIdx.x] += red[threadIdx.x + st];
        __syncthreads();
    }
    float sc = g[row] / sqrtf(red[0]);
    for (int k = threadIdx.x; k < R; k += 256) {
        unsigned short h, l;
        bf_split(vr[k] * sc, h, l);
        oh[(size_t)row * R + k] = __ushort_as_bfloat16(h);
        ol[(size_t)row * R + k] = __ushort_as_bfloat16(l);
    }
}

// ---------- w2[:,32:] split ----------
__global__ void k_wsplit(const float* __restrict__ w2, __nv_bfloat16* __restrict__ oh,
                         __nv_bfloat16* __restrict__ ol) {
    int r = blockIdx.x;
    for (int k = threadIdx.x; k < 1024; k += 256) {
        unsigned short h, l;
        bf_split(w2[(size_t)r * 1056 + 32 + k], h, l);
        oh[(size_t)r * 1024 + k] = __ushort_as_bfloat16(h);
        ol[(size_t)r * 1024 + k] = __ushort_as_bfloat16(l);
    }
}

// ---------- c1 = w1[:,32:] @ feat + b1 ----------
__global__ void k_c1(const float* __restrict__ w1, const float* __restrict__ b1,
                     const float* __restrict__ feat, float* __restrict__ c1) {
    int o = blockIdx.x * 8 + (threadIdx.x >> 5);
    int lane = threadIdx.x & 31;
    const float* wr = w1 + (size_t)o * 2080 + 32;
    float s = 0.f;
    for (int k = lane; k < 2048; k += 32) s += wr[k] * feat[k];
#pragma unroll
    for (int off = 16; off; off >>= 1) s += __shfl_xor_sync(0xffffffffu, s, off);
    if (lane == 0) c1[o] = s + b1[o];
}

// ---------- K=32 fp32 GEMM: MODE0 -> lrelu + bf16 split; MODE1 -> fp32 out ----------
template <int MODE>
__global__ void __launch_bounds__(256) k_gemm32(
    const float* __restrict__ A, const float* __restrict__ W, int ldw,
    const float* __restrict__ bias,
    __nv_bfloat16* __restrict__ oh, __nv_bfloat16* __restrict__ ol,
    float* __restrict__ of, int ldc, int O) {
    __shared__ float As[8][32];
    int r0 = blockIdx.x * 8;
    As[threadIdx.x >> 5][threadIdx.x & 31] = A[(size_t)(r0 + (threadIdx.x >> 5)) * 32 + (threadIdx.x & 31)];
    __syncthreads();
    int wrow = threadIdx.x >> 5, lane = threadIdx.x & 31;
    float a[32];
#pragma unroll
    for (int k = 0; k < 32; k++) a[k] = As[wrow][k];
    size_t row = r0 + wrow;
    for (int cb = 0; cb < O; cb += 256) {
        float v[8];
#pragma unroll
        for (int j = 0; j < 8; j++) {
            int col = cb + lane * 8 + j;
            const float4* wr = (const float4*)(W + (size_t)col * ldw);
            float s = 0.f;
#pragma unroll
            for (int q = 0; q < 8; q++) {
                float4 wv = wr[q];
                s += a[q*4] * wv.x + a[q*4+1] * wv.y + a[q*4+2] * wv.z + a[q*4+3] * wv.w;
            }
            v[j] = s + bias[col];
            if (MODE == 0) v[j] = lrelu(v[j]);
        }
        if (MODE == 0) {
            unsigned short hh[8], ll[8];
#pragma unroll
            for (int j = 0; j < 8; j++) bf_split(v[j], hh[j], ll[j]);
            *(uint4*)(oh + row * ldc + cb + lane * 8) = *(uint4*)hh;
            *(uint4*)(ol + row * ldc + cb + lane * 8) = *(uint4*)ll;
        } else {
            float* dst = of + row * ldc + cb + lane * 8;
            *(float4*)dst = *(float4*)v;
            *(float4*)(dst + 4) = *(float4*)(v + 4);
        }
    }
}

// ---------- mma.sync bf16x3 GEMM: C = epi(A[65536,K] @ W[O,K]^T) ----------
// MODE 0: out = (Rh+Rl) + lrelu(acc + bias)   -> bf16 hi/lo (coupling, in-place safe)
// MODE 1: out = lrelu(acc + Rf)               -> bf16 hi/lo (concat pass; Rf has bias)
// CTA tile 128x128, BK=64, 512 threads, warp tile 32x32, 3-stage cp.async ring,
// ONE __syncthreads per chunk. 144B row pitch (conflict-free ldmatrix/cp.async).
#define TPITCH 144u      // bytes per padded 64-elt bf16 row
#define TBYTES 18432u    // one 128-row tile
#define SBYTES 73728u    // 4 tiles (Ah, Al, Wh, Wl) = one stage
#define NSTAGE 3
template <int MODE>
__global__ void __launch_bounds__(512, 1) tgemm(
    const __nv_bfloat16* __restrict__ Ah, const __nv_bfloat16* __restrict__ Al, int lda,
    const __nv_bfloat16* __restrict__ Wh, const __nv_bfloat16* __restrict__ Wl, int ldw,
    const float* __restrict__ bias,
    const __nv_bfloat16* __restrict__ Rh, const __nv_bfloat16* __restrict__ Rl,
    const float* __restrict__ Rf, int ldr,
    __nv_bfloat16* __restrict__ Coh, __nv_bfloat16* __restrict__ Col, int ldc, int K) {
    extern __shared__ char smem[];
    uint32_t sb = smem_u32(smem);
    int tid = threadIdx.x;
    int lane = tid & 31, wid = tid >> 5;
    int wm = wid & 3, wn = wid >> 2;     // 4 x 4 warp grid, 32x32 tiles
    int row0 = blockIdx.y * 128, col0 = blockIdx.x * 128;

    float acc[2][4][4];
#pragma unroll
    for (int i = 0; i < 2; i++)
#pragma unroll
        for (int j = 0; j < 4; j++)
#pragma unroll
            for (int q = 0; q < 4; q++) acc[i][j][q] = 0.f;

    // ldmatrix lane->address precompute
    int arow = lane & 15, acol = (lane & 16) >> 1;                 // A frags 16x16
    int brow = (lane & 7) + ((lane & 16) >> 1), bcol = lane & 8;   // B frags 16x16

    // cp.async: per tile 128 rows x 8 16B-chunks = 1024 chunks; thread t does t, t+512
    int r0c = tid >> 3, q0c = tid & 7;           // chunk tid
    int r1c = (tid + 512) >> 3, q1c = tid & 7;   // chunk tid+512 (q same since +512 = +64 rows)
    uint32_t so0 = (uint32_t)r0c * TPITCH + (uint32_t)q0c * 16u;
    uint32_t so1 = (uint32_t)r1c * TPITCH + (uint32_t)q1c * 16u;

    int nch = K >> 6;
    auto issue = [&](int c) {
        uint32_t base = sb + (uint32_t)(c % NSTAGE) * SBYTES;
        int kc = c << 6;
        size_t ga0 = (size_t)(row0 + r0c) * lda + kc + q0c * 8;
        size_t ga1 = (size_t)(row0 + r1c) * lda + kc + q1c * 8;
        size_t gw0 = (size_t)(col0 + r0c) * ldw + kc + q0c * 8;
        size_t gw1 = (size_t)(col0 + r1c) * ldw + kc + q1c * 8;
        cpa(base + so0,              Ah + ga0);
        cpa(base + so1,              Ah + ga1);
        cpa(base + TBYTES + so0,     Al + ga0);
        cpa(base + TBYTES + so1,     Al + ga1);
        cpa(base + 2 * TBYTES + so0, Wh + gw0);
        cpa(base + 2 * TBYTES + so1, Wh + gw1);
        cpa(base + 3 * TBYTES + so0, Wl + gw0);
        cpa(base + 3 * TBYTES + so1, Wl + gw1);
        CP_COMMIT();
    };

    issue(0);
    if (nch > 1) issue(1);
    for (int c = 0; c < nch; c++) {
        if (c + 1 < nch) cp_wait<1>(); else cp_wait<0>();
        __syncthreads();
        if (c + 2 < nch) issue(c + 2);
        uint32_t base = sb + (uint32_t)(c % NSTAGE) * SBYTES;
#pragma unroll
        for (int kk = 0; kk < 4; kk++) {
            uint32_t ah[2][4], av[2][4];
#pragma unroll
            for (int mi = 0; mi < 2; mi++) {
                uint32_t off = (uint32_t)(wm * 32 + mi * 16 + arow) * TPITCH + (uint32_t)(kk * 16 + acol) * 2u;
                ldmx4(ah[mi], base + off);
                ldmx4(av[mi], base + TBYTES + off);
            }
            uint32_t bh[2][4], bv[2][4];
#pragma unroll
            for (int pi = 0; pi < 2; pi++) {
                uint32_t off = (uint32_t)(wn * 32 + pi * 16 + brow) * TPITCH + (uint32_t)(kk * 16 + bcol) * 2u;
                ldmx4(bh[pi], base + 2 * TBYTES + off);
                ldmx4(bv[pi], base + 3 * TBYTES + off);
            }
#pragma unroll
            for (int mi = 0; mi < 2; mi++)
#pragma unroll
                for (int ni = 0; ni < 4; ni++) {
                    const uint32_t* bhp = &bh[ni >> 1][(ni & 1) << 1];
                    const uint32_t* bvp = &bv[ni >> 1][(ni & 1) << 1];
                    mma16816(acc[mi][ni], ah[mi], bhp);   // Ah*Wh
                    mma16816(acc[mi][ni], ah[mi], bvp);   // Ah*Wl
                    mma16816(acc[mi][ni], av[mi], bhp);   // Al*Wh
                }
        }
    }

    // epilogue
    int gid = lane >> 2, tig = lane & 3;
#pragma unroll
    for (int mi = 0; mi < 2; mi++) {
#pragma unroll
        for (int ni = 0; ni < 4; ni++) {
            int col = col0 + wn * 32 + ni * 8 + tig * 2;
#pragma unroll
            for (int h = 0; h < 2; h++) {
                size_t r = (size_t)(row0 + wm * 32 + mi * 16 + gid + h * 8);
                float v0 = acc[mi][ni][h * 2], v1 = acc[mi][ni][h * 2 + 1];
                if (MODE == 0) {
                    float2 bb = *(const float2*)(bias + col);
                    v0 = lrelu(v0 + bb.x);
                    v1 = lrelu(v1 + bb.y);
                    __nv_bfloat162 hh = *(const __nv_bfloat162*)(Rh + r * ldr + col);
                    __nv_bfloat162 ll = *(const __nv_bfloat162*)(Rl + r * ldr + col);
                    v0 += __bfloat162float(hh.x) + __bfloat162float(ll.x);
                    v1 += __bfloat162float(hh.y) + __bfloat162float(ll.y);
                } else {
                    float2 rf = *(const float2*)(Rf + r * ldr + col);
                    v0 = lrelu(v0 + rf.x);
                    v1 = lrelu(v1 + rf.y);
                }
                unsigned short h0, l0, h1, l1;
                bf_split(v0, h0, l0);
                bf_split(v1, h1, l1);
                *(uint32_t*)(Coh + r * ldc + col) = (uint32_t)h0 | ((uint32_t)h1 << 16);
                *(uint32_t*)(Col + r * ldc + col) = (uint32_t)l0 | ((uint32_t)l1 << 16);
            }
        }
    }
}

// ---------- final rgb head ----------
__global__ void k_final(const __nv_bfloat16* __restrict__ hh, const __nv_bfloat16* __restrict__ hl,
                        const float* __restrict__ w3, const float* __restrict__ b3,
                        float* __restrict__ out) {
    int gw = (blockIdx.x * blockDim.x + threadIdx.x) >> 5;
    int lane = threadIdx.x & 31;
    const __nv_bfloat16* rh = hh + (size_t)gw * 512;
    const __nv_bfloat16* rl = hl + (size_t)gw * 512;
    float s0 = 0.f, s1 = 0.f, s2 = 0.f;
    for (int k = lane; k < 512; k += 32) {
        float h = __bfloat162float(rh[k]) + __bfloat162float(rl[k]);
        s0 += h * w3[k];
        s1 += h * w3[512 + k];
        s2 += h * w3[1024 + k];
    }
#pragma unroll
    for (int off = 16; off; off >>= 1) {
        s0 += __shfl_xor_sync(0xffffffffu, s0, off);
        s1 += __shfl_xor_sync(0xffffffffu, s1, off);
        s2 += __shfl_xor_sync(0xffffffffu, s2, off);
    }
    if (lane == 0) {
        out[gw]            = 1.1f / (1.f + expf(-(s0 + b3[0]))) - 0.05f;
        out[NPIX + gw]     = 1.1f / (1.f + expf(-(s1 + b3[1]))) - 0.05f;
        out[2 * NPIX + gw] = 1.1f / (1.f + expf(-(s2 + b3[2]))) - 0.05f;
    }
}

// ---------- host ----------
#define TG_SMEM 221184
extern "C" void kernel_launch(void* const* d_in, const int* in_sizes, int n_in,
                              void* d_out, int out_size) {
    const float* feature = (const float*)d_in[0];
    const float* cw1 = (const float*)d_in[1];  const float* cb1 = (const float*)d_in[2];
    const float* cw2 = (const float*)d_in[3];  const float* cb2 = (const float*)d_in[4];
    const float* cw3 = (const float*)d_in[5];  const float* cb3 = (const float*)d_in[6];
    const float* cw4 = (const float*)d_in[7];  const float* cb4 = (const float*)d_in[8];
    const float* cw5 = (const float*)d_in[9];  const float* cb5 = (const float*)d_in[10];
    const float* w1  = (const float*)d_in[11]; const float* b1  = (const float*)d_in[12];
    const float* m1_vf = (const float*)d_in[13]; const float* m1_gf = (const float*)d_in[14]; const float* m1_bf = (const float*)d_in[15];
    const float* m1_vg = (const float*)d_in[16]; const float* m1_gg = (const float*)d_in[17]; const float* m1_bg = (const float*)d_in[18];
    const float* w2  = (const float*)d_in[19]; const float* b2  = (const float*)d_in[20];
    const float* m2_vf = (const float*)d_in[21]; const float* m2_gf = (const float*)d_in[22]; const float* m2_bf = (const float*)d_in[23];
    const float* m2_vg = (const float*)d_in[24]; const float* m2_gg = (const float*)d_in[25]; const float* m2_bg = (const float*)d_in[26];
    const float* w3  = (const float*)d_in[27]; const float* b3  = (const float*)d_in[28];
    float* out = (float*)d_out;

    float *grid, *h2f, *cA, *cB, *feat, *c1;
    __nv_bfloat16 *midh, *midl, *h2bh, *h2bl;
    __nv_bfloat16 *wf1h, *wf1l, *wg1h, *wg1l, *wf2h, *wf2l, *wg2h, *wg2l, *w2mh, *w2ml;
    cudaGetSymbolAddress((void**)&grid, g_grid);
    cudaGetSymbolAddress((void**)&h2f,  g_h2f);
    cudaGetSymbolAddress((void**)&cA,   g_convA);
    cudaGetSymbolAddress((void**)&cB,   g_convB);
    cudaGetSymbolAddress((void**)&feat, g_feat);
    cudaGetSymbolAddress((void**)&c1,   g_c1v);
    cudaGetSymbolAddress((void**)&midh, g_midh);
    cudaGetSymbolAddress((void**)&midl, g_midl);
    cudaGetSymbolAddress((void**)&h2bh, g_h2bh);
    cudaGetSymbolAddress((void**)&h2bl, g_h2bl);
    cudaGetSymbolAddress((void**)&wf1h, g_wf1h); cudaGetSymbolAddress((void**)&wf1l, g_wf1l);
    cudaGetSymbolAddress((void**)&wg1h, g_wg1h); cudaGetSymbolAddress((void**)&wg1l, g_wg1l);
    cudaGetSymbolAddress((void**)&wf2h, g_wf2h); cudaGetSymbolAddress((void**)&wf2l, g_wf2l);
    cudaGetSymbolAddress((void**)&wg2h, g_wg2h); cudaGetSymbolAddress((void**)&wg2l, g_wg2l);
    cudaGetSymbolAddress((void**)&w2mh, g_w2mh); cudaGetSymbolAddress((void**)&w2ml, g_w2ml);

    cudaFuncSetAttribute(tgemm<0>, cudaFuncAttributeMaxDynamicSharedMemorySize, TG_SMEM);
    cudaFuncSetAttribute(tgemm<1>, cudaFuncAttributeMaxDynamicSharedMemorySize, TG_SMEM);

    k_gridgen<<<NPIX / 256, 256>>>(grid);
    k_conv<<<768, 256, 448 * 9 * 4>>>(feature, cw1, cb1, cA, 448, 768, 8, 8, 8, 8, 1, 4);
    k_conv<<<768, 256, 256 * 9 * 4>>>(cA, cw2, cb2, cB, 256, 768, 8, 8, 8, 8, 1, 3);
    k_conv<<<768, 256, 384 * 9 * 4>>>(cB, cw3, cb3, cA, 384, 768, 8, 8, 8, 8, 1, 2);
    k_conv<<<768, 256, 256 * 9 * 4>>>(cA, cw4, cb4, cB, 256, 768, 8, 8, 6, 6, 0, 3);
    k_conv<<<128, 256, 768 * 9 * 4>>>(cB, cw5, cb5, feat, 768, 128, 6, 6, 4, 4, 0, 1);
    k_c1<<<128, 256>>>(w1, b1, feat, c1);
    k_wnorm_s<<<4096, 256>>>(m1_vf, m1_gf, wf1h, wf1l, 512);
    k_wnorm_s<<<4096, 256>>>(m1_vg, m1_gg, wg1h, wg1l, 512);
    k_wnorm_s<<<2048, 256>>>(m2_vf, m2_gf, wf2h, wf2l, 256);
    k_wnorm_s<<<2048, 256>>>(m2_vg, m2_gg, wg2h, wg2l, 256);
    k_wsplit<<<512, 256>>>(w2, w2mh, w2ml);

    // mid = lrelu(grid @ w1[:, :32]^T + c1)  -> bf16 hi/lo [65536,1024]
    k_gemm32<0><<<NPIX / 8, 256>>>(grid, w1, 2080, c1, midh, midl, nullptr, 1024, 1024);

    // coupling stack 1 (512-wide halves, in-place on mid pair)
    for (int s = 0; s < 8; s++) {
        tgemm<0><<<dim3(4, 512), 512, TG_SMEM>>>(
            midh + 512, midl + 512, 1024, wf1h + (size_t)s * 262144, wf1l + (size_t)s * 262144, 512,
            m1_bf + s * 512, midh, midl, nullptr, 1024, midh, midl, 1024, 512);
        tgemm<0><<<dim3(4, 512), 512, TG_SMEM>>>(
            midh, midl, 1024, wg1h + (size_t)s * 262144, wg1l + (size_t)s * 262144, 512,
            m1_bg + s * 512, midh + 512, midl + 512, nullptr, 1024, midh + 512, midl + 512, 1024, 512);
    }

    // h2 = lrelu(gridpart(+b2) + mid @ w2[:,32:]^T)
    k_gemm32<1><<<NPIX / 8, 256>>>(grid, w2, 1056, b2, nullptr, nullptr, h2f, 512, 512);
    tgemm<1><<<dim3(4, 512), 512, TG_SMEM>>>(
        midh, midl, 1024, w2mh, w2ml, 1024, nullptr, nullptr, nullptr, h2f, 512,
        h2bh, h2bl, 512, 1024);

    // coupling stack 2 (256-wide halves)
    for (int s = 0; s < 8; s++) {
        tgemm<0><<<dim3(2, 512), 512, TG_SMEM>>>(
            h2bh + 256, h2bl + 256, 512, wf2h + (size_t)s * 65536, wf2l + (size_t)s * 65536, 256,
            m2_bf + s * 256, h2bh, h2bl, nullptr, 512, h2bh, h2bl, 512, 256);
        tgemm<0><<<dim3(2, 512), 512, TG_SMEM>>>(
            h2bh, h2bl, 512, wg2h + (size_t)s * 65536, wg2l + (size_t)s * 65536, 256,
            m2_bg + s * 256, h2bh + 256, h2bl + 256, nullptr, 512, h2bh + 256, h2bl + 256, 512, 256);
    }

    k_final<<<NPIX / 8, 256>>>(h2bh, h2bl, w3, b3, out);
}

// round 12
// speedup vs baseline: 1.2093x; 1.2093x over previous
#include <cuda_runtime.h>
#include <cuda_fp16.h>
#include <math.h>
#include <stdint.h>

#define NPIX 65536

// ---------- static scratch ----------
__device__ float g_grid[NPIX * 32];
__device__ float g_h2f[33554432];                     // [65536,512] fp32 partial
__device__ __align__(16) __half g_midh[67108864];     // [65536,1024] hi
__device__ __align__(16) __half g_midl[67108864];     // lo
__device__ __align__(16) __half g_h2bh[33554432];     // [65536,512]
__device__ __align__(16) __half g_h2bl[33554432];
__device__ __align__(16) __half g_wf1h[2097152], g_wf1l[2097152];
__device__ __align__(16) __half g_wg1h[2097152], g_wg1l[2097152];
__device__ __align__(16) __half g_wf2h[524288],  g_wf2l[524288];
__device__ __align__(16) __half g_wg2h[524288],  g_wg2l[524288];
__device__ __align__(16) __half g_w2mh[524288],  g_w2ml[524288];
__device__ float g_convA[768 * 64];
__device__ float g_convB[768 * 64];
__device__ float g_feat[2048];
__device__ float g_c1v[1024];

__device__ __forceinline__ float lrelu(float x) { return x > 0.f ? x : 0.01f * x; }
__device__ __forceinline__ void hf_split(float v, unsigned short& h, unsigned short& l) {
    __half hb = __float2half(v);
    l = __half_as_ushort(__float2half(v - __half2float(hb)));
    h = __half_as_ushort(hb);
}

// ---------- PTX helpers (baseline sm_80 features only) ----------
__device__ __forceinline__ uint32_t smem_u32(const void* p) {
    uint32_t a;
    asm("{ .reg .u64 t; cvta.to.shared.u64 t, %1; cvt.u32.u64 %0, t; }" : "=r"(a) : "l"(p));
    return a;
}
__device__ __forceinline__ void cpa(uint32_t dst, const void* src) {
    asm volatile("cp.async.ca.shared.global [%0], [%1], 16;" :: "r"(dst), "l"(src));
}
#define CP_COMMIT() asm volatile("cp.async.commit_group;" ::: "memory")
template <int N> __device__ __forceinline__ void cp_wait() {
    asm volatile("cp.async.wait_group %0;" :: "n"(N) : "memory");
}
__device__ __forceinline__ void ldmx4(uint32_t* r, uint32_t addr) {
    asm volatile("ldmatrix.sync.aligned.m8n8.x4.shared.b16 {%0,%1,%2,%3}, [%4];"
        : "=r"(r[0]), "=r"(r[1]), "=r"(r[2]), "=r"(r[3]) : "r"(addr));
}
__device__ __forceinline__ void mma16816(float* d, const uint32_t* a, const uint32_t* b) {
    asm volatile(
        "mma.sync.aligned.m16n8k16.row.col.f32.f16.f16.f32 "
        "{%0,%1,%2,%3}, {%4,%5,%6,%7}, {%8,%9}, {%0,%1,%2,%3};"
        : "+f"(d[0]), "+f"(d[1]), "+f"(d[2]), "+f"(d[3])
        : "r"(a[0]), "r"(a[1]), "r"(a[2]), "r"(a[3]), "r"(b[0]), "r"(b[1]));
}

// ---------- grid features ----------
__global__ void k_gridgen(float* __restrict__ g) {
    int p = blockIdx.x * blockDim.x + threadIdx.x;
    float fi = (float)((p >> 8) - 128);
    float fj = (float)((p & 255) - 128);
    float* row = g + (size_t)p * 32;
#pragma unroll
    for (int k = 0; k < 16; k++) {
        float s = exp2f(0.5f * k - 8.0f);
        row[2 * k]     = sinpif(fi * s);
        row[2 * k + 1] = sinpif(fj * s);
    }
}

// ---------- 3x3 grouped conv, 256 thr, 4-way ci slices ----------
__global__ void k_conv(const float* __restrict__ in, const float* __restrict__ w,
                       const float* __restrict__ b, float* __restrict__ out,
                       int Cipg, int Cout, int Hin, int Win, int Hout, int Wout,
                       int pad, int groups) {
    extern __shared__ float ws[];
    __shared__ float red[4][64];
    int o = blockIdx.x;
    int opg = Cout / groups;
    const float* inb = in + (size_t)(o / opg) * Cipg * Hin * Win;
    const float* wb = w + (size_t)o * Cipg * 9;
    int nw = Cipg * 9;
    for (int i = threadIdx.x; i < nw; i += blockDim.x) ws[i] = wb[i];
    __syncthreads();
    int np = Hout * Wout;
    int sl = threadIdx.x >> 6, p = threadIdx.x & 63;
    int cps = Cipg >> 2;
    float acc = 0.f;
    if (p < np) {
        int y = p / Wout, x = p % Wout;
        for (int ci = sl * cps; ci < (sl + 1) * cps; ci++) {
            const float* ip = inb + (size_t)ci * Hin * Win;
            const float* wp = ws + ci * 9;
#pragma unroll
            for (int ky = 0; ky < 3; ky++) {
                int iy = y + ky - pad;
                if ((unsigned)iy < (unsigned)Hin) {
#pragma unroll
                    for (int kx = 0; kx < 3; kx++) {
                        int ix = x + kx - pad;
                        if ((unsigned)ix < (unsigned)Win)
                            acc += ip[iy * Win + ix] * wp[ky * 3 + kx];
                    }
                }
            }
        }
    }
    red[sl][p] = acc;
    __syncthreads();
    if (sl == 0 && p < np)
        out[(size_t)o * np + p] = lrelu(red[0][p] + red[1][p] + red[2][p] + red[3][p] + b[o]);
}

// ---------- weight norm + fp16 split ----------
__global__ void k_wnorm_s(const float* __restrict__ v, const float* __restrict__ g,
                          __half* __restrict__ oh, __half* __restrict__ ol, int R) {
    int row = blockIdx.x;
    const float* vr = v + (size_t)row * R;
    float s = 0.f;
    for (int k = threadIdx.x; k < R; k += 256) { float x = vr[k]; s += x * x; }
    __shared__ float red[256];
    red[threadIdx.x] = s;
    __syncthreads();
    for (int st = 128; st > 0; st >>= 1) {
        if (threadIdx.x < st) red[threadIdx.x] += red[threadIdx.x + st];
        __syncthreads();
    }
    float sc = g[row] / sqrtf(red[0]);
    for (int k = threadIdx.x; k < R; k += 256) {
        unsigned short h, l;
        hf_split(vr[k] * sc, h, l);
        oh[(size_t)row * R + k] = __ushort_as_half(h);
        ol[(size_t)row * R + k] = __ushort_as_half(l);
    }
}

// ---------- w2[:,32:] split ----------
__global__ void k_wsplit(const float* __restrict__ w2, __half* __restrict__ oh,
                         __half* __restrict__ ol) {
    int r = blockIdx.x;
    for (int k = threadIdx.x; k < 1024; k += 256) {
        unsigned short h, l;
        hf_split(w2[(size_t)r * 1056 + 32 + k], h, l);
        oh[(size_t)r * 1024 + k] = __ushort_as_half(h);
        ol[(size_t)r * 1024 + k] = __ushort_as_half(l);
    }
}

// ---------- c1 = w1[:,32:] @ feat + b1 ----------
__global__ void k_c1(const float* __restrict__ w1, const float* __restrict__ b1,
                     const float* __restrict__ feat, float* __restrict__ c1) {
    int o = blockIdx.x * 8 + (threadIdx.x >> 5);
    int lane = threadIdx.x & 31;
    const float* wr = w1 + (size_t)o * 2080 + 32;
    float s = 0.f;
    for (int k = lane; k < 2048; k += 32) s += wr[k] * feat[k];
#pragma unroll
    for (int off = 16; off; off >>= 1) s += __shfl_xor_sync(0xffffffffu, s, off);
    if (lane == 0) c1[o] = s + b1[o];
}

// ---------- K=32 fp32 GEMM: MODE0 -> lrelu + fp16 split; MODE1 -> fp32 out ----------
template <int MODE>
__global__ void __launch_bounds__(256) k_gemm32(
    const float* __restrict__ A, const float* __restrict__ W, int ldw,
    const float* __restrict__ bias,
    __half* __restrict__ oh, __half* __restrict__ ol,
    float* __restrict__ of, int ldc, int O) {
    __shared__ float As[8][32];
    int r0 = blockIdx.x * 8;
    As[threadIdx.x >> 5][threadIdx.x & 31] = A[(size_t)(r0 + (threadIdx.x >> 5)) * 32 + (threadIdx.x & 31)];
    __syncthreads();
    int wrow = threadIdx.x >> 5, lane = threadIdx.x & 31;
    float a[32];
#pragma unroll
    for (int k = 0; k < 32; k++) a[k] = As[wrow][k];
    size_t row = r0 + wrow;
    for (int cb = 0; cb < O; cb += 256) {
        float v[8];
#pragma unroll
        for (int j = 0; j < 8; j++) {
            int col = cb + lane * 8 + j;
            const float4* wr = (const float4*)(W + (size_t)col * ldw);
            float s = 0.f;
#pragma unroll
            for (int q = 0; q < 8; q++) {
                float4 wv = wr[q];
                s += a[q*4] * wv.x + a[q*4+1] * wv.y + a[q*4+2] * wv.z + a[q*4+3] * wv.w;
            }
            v[j] = s + bias[col];
            if (MODE == 0) v[j] = lrelu(v[j]);
        }
        if (MODE == 0) {
            unsigned short hh[8], ll[8];
#pragma unroll
            for (int j = 0; j < 8; j++) hf_split(v[j], hh[j], ll[j]);
            *(uint4*)(oh + row * ldc + cb + lane * 8) = *(uint4*)hh;
            *(uint4*)(ol + row * ldc + cb + lane * 8) = *(uint4*)ll;
        } else {
            float* dst = of + row * ldc + cb + lane * 8;
            *(float4*)dst = *(float4*)v;
            *(float4*)(dst + 4) = *(float4*)(v + 4);
        }
    }
}

// ---------- mma.sync fp16x2 GEMM: C = epi(Ah[65536,K] @ (Wh+Wl)[O,K]^T) ----------
// A consumed as fp16 hi only (Al carried in residual, not MMA'd). 2 MMAs/cell.
// MODE 0: out = (Rh+Rl) + lrelu(acc + bias)   -> fp16 hi/lo (coupling, in-place safe)
// MODE 1: out = lrelu(acc + Rf)               -> fp16 hi/lo (concat pass; Rf has bias)
// CTA tile 128x128, BK=32, 512 threads, warp tile 32x32, 2-stage.
#define TPITCH 80u       // bytes per padded 32-elt fp16 row
#define TBYTES 10240u    // one 128-row tile
#define SBYTES 30720u    // 3 tiles (Ah, Wh, Wl) = one stage
template <int MODE>
__global__ void __launch_bounds__(512, 1) tgemm(
    const __half* __restrict__ Ah, int lda,
    const __half* __restrict__ Wh, const __half* __restrict__ Wl, int ldw,
    const float* __restrict__ bias,
    const __half* __restrict__ Rh, const __half* __restrict__ Rl,
    const float* __restrict__ Rf, int ldr,
    __half* __restrict__ Coh, __half* __restrict__ Col, int ldc, int K) {
    extern __shared__ char smem[];
    uint32_t sb = smem_u32(smem);
    int tid = threadIdx.x;
    int lane = tid & 31, wid = tid >> 5;
    int wm = wid & 3, wn = wid >> 2;     // 4 x 4 warp grid, 32x32 tiles
    int row0 = blockIdx.y * 128, col0 = blockIdx.x * 128;

    float acc[2][4][4];
#pragma unroll
    for (int i = 0; i < 2; i++)
#pragma unroll
        for (int j = 0; j < 4; j++)
#pragma unroll
            for (int q = 0; q < 4; q++) acc[i][j][q] = 0.f;

    // ldmatrix lane->address precompute
    int arow = lane & 15, acol = (lane & 16) >> 1;                 // A frags 16x16
    int brow = (lane & 7) + ((lane & 16) >> 1), bcol = lane & 8;   // B frags 16x16

    // per-thread cp.async: 1x16B per tile per stage (128 rows x 4 chunks = 512 = nthreads)
    int crow = tid >> 2, cq = tid & 3;
    uint32_t cso = (uint32_t)crow * TPITCH + (uint32_t)cq * 16u;

    int nch = K >> 5;
    auto issue = [&](int c) {
        uint32_t base = sb + (uint32_t)(c & 1) * SBYTES;
        int kc = c << 5;
        size_t ga = (size_t)(row0 + crow) * lda + kc + cq * 8;
        size_t gw = (size_t)(col0 + crow) * ldw + kc + cq * 8;
        cpa(base + cso,              Ah + ga);
        cpa(base + TBYTES + cso,     Wh + gw);
        cpa(base + 2 * TBYTES + cso, Wl + gw);
        CP_COMMIT();
    };

    issue(0);
    for (int c = 0; c < nch; c++) {
        if (c + 1 < nch) { issue(c + 1); cp_wait<1>(); } else { cp_wait<0>(); }
        __syncthreads();
        uint32_t base = sb + (uint32_t)(c & 1) * SBYTES;
#pragma unroll
        for (int kk = 0; kk < 2; kk++) {
            uint32_t ah[2][4];
#pragma unroll
            for (int mi = 0; mi < 2; mi++) {
                uint32_t off = (uint32_t)(wm * 32 + mi * 16 + arow) * TPITCH + (uint32_t)(kk * 16 + acol) * 2u;
                ldmx4(ah[mi], base + off);
            }
            uint32_t bh[2][4], bv[2][4];
#pragma unroll
            for (int pi = 0; pi < 2; pi++) {
                uint32_t off = (uint32_t)(wn * 32 + pi * 16 + brow) * TPITCH + (uint32_t)(kk * 16 + bcol) * 2u;
                ldmx4(bh[pi], base + TBYTES + off);
                ldmx4(bv[pi], base + 2 * TBYTES + off);
            }
#pragma unroll
            for (int mi = 0; mi < 2; mi++)
#pragma unroll
                for (int ni = 0; ni < 4; ni++) {
                    const uint32_t* bhp = &bh[ni >> 1][(ni & 1) << 1];
                    const uint32_t* bvp = &bv[ni >> 1][(ni & 1) << 1];
                    mma16816(acc[mi][ni], ah[mi], bhp);   // Ah*Wh
                    mma16816(acc[mi][ni], ah[mi], bvp);   // Ah*Wl
                }
        }
        __syncthreads();
    }

    // epilogue
    int gid = lane >> 2, tig = lane & 3;
#pragma unroll
    for (int mi = 0; mi < 2; mi++) {
#pragma unroll
        for (int ni = 0; ni < 4; ni++) {
            int col = col0 + wn * 32 + ni * 8 + tig * 2;
#pragma unroll
            for (int h = 0; h < 2; h++) {
                size_t r = (size_t)(row0 + wm * 32 + mi * 16 + gid + h * 8);
                float v0 = acc[mi][ni][h * 2], v1 = acc[mi][ni][h * 2 + 1];
                if (MODE == 0) {
                    float2 bb = *(const float2*)(bias + col);
                    v0 = lrelu(v0 + bb.x);
                    v1 = lrelu(v1 + bb.y);
                    __half2 hh = *(const __half2*)(Rh + r * ldr + col);
                    __half2 ll = *(const __half2*)(Rl + r * ldr + col);
                    v0 += __half2float(hh.x) + __half2float(ll.x);
                    v1 += __half2float(hh.y) + __half2float(ll.y);
                } else {
                    float2 rf = *(const float2*)(Rf + r * ldr + col);
                    v0 = lrelu(v0 + rf.x);
                    v1 = lrelu(v1 + rf.y);
                }
                unsigned short h0, l0, h1, l1;
                hf_split(v0, h0, l0);
                hf_split(v1, h1, l1);
                *(uint32_t*)(Coh + r * ldc + col) = (uint32_t)h0 | ((uint32_t)h1 << 16);
                *(uint32_t*)(Col + r * ldc + col) = (uint32_t)l0 | ((uint32_t)l1 << 16);
            }
        }
    }
}

// ---------- final rgb head ----------
__global__ void k_final(const __half* __restrict__ hh, const __half* __restrict__ hl,
                        const float* __restrict__ w3, const float* __restrict__ b3,
                        float* __restrict__ out) {
    int gw = (blockIdx.x * blockDim.x + threadIdx.x) >> 5;
    int lane = threadIdx.x & 31;
    const __half* rh = hh + (size_t)gw * 512;
    const __half* rl = hl + (size_t)gw * 512;
    float s0 = 0.f, s1 = 0.f, s2 = 0.f;
    for (int k = lane; k < 512; k += 32) {
        float h = __half2float(rh[k]) + __half2float(rl[k]);
        s0 += h * w3[k];
        s1 += h * w3[512 + k];
        s2 += h * w3[1024 + k];
    }
#pragma unroll
    for (int off = 16; off; off >>= 1) {
        s0 += __shfl_xor_sync(0xffffffffu, s0, off);
        s1 += __shfl_xor_sync(0xffffffffu, s1, off);
        s2 += __shfl_xor_sync(0xffffffffu, s2, off);
    }
    if (lane == 0) {
        out[gw]            = 1.1f / (1.f + expf(-(s0 + b3[0]))) - 0.05f;
        out[NPIX + gw]     = 1.1f / (1.f + expf(-(s1 + b3[1]))) - 0.05f;
        out[2 * NPIX + gw] = 1.1f / (1.f + expf(-(s2 + b3[2]))) - 0.05f;
    }
}

// ---------- host ----------
#define TG_SMEM 61440
extern "C" void kernel_launch(void* const* d_in, const int* in_sizes, int n_in,
                              void* d_out, int out_size) {
    const float* feature = (const float*)d_in[0];
    const float* cw1 = (const float*)d_in[1];  const float* cb1 = (const float*)d_in[2];
    const float* cw2 = (const float*)d_in[3];  const float* cb2 = (const float*)d_in[4];
    const float* cw3 = (const float*)d_in[5];  const float* cb3 = (const float*)d_in[6];
    const float* cw4 = (const float*)d_in[7];  const float* cb4 = (const float*)d_in[8];
    const float* cw5 = (const float*)d_in[9];  const float* cb5 = (const float*)d_in[10];
    const float* w1  = (const float*)d_in[11]; const float* b1  = (const float*)d_in[12];
    const float* m1_vf = (const float*)d_in[13]; const float* m1_gf = (const float*)d_in[14]; const float* m1_bf = (const float*)d_in[15];
    const float* m1_vg = (const float*)d_in[16]; const float* m1_gg = (const float*)d_in[17]; const float* m1_bg = (const float*)d_in[18];
    const float* w2  = (const float*)d_in[19]; const float* b2  = (const float*)d_in[20];
    const float* m2_vf = (const float*)d_in[21]; const float* m2_gf = (const float*)d_in[22]; const float* m2_bf = (const float*)d_in[23];
    const float* m2_vg = (const float*)d_in[24]; const float* m2_gg = (const float*)d_in[25]; const float* m2_bg = (const float*)d_in[26];
    const float* w3  = (const float*)d_in[27]; const float* b3  = (const float*)d_in[28];
    float* out = (float*)d_out;

    float *grid, *h2f, *cA, *cB, *feat, *c1;
    __half *midh, *midl, *h2bh, *h2bl;
    __half *wf1h, *wf1l, *wg1h, *wg1l, *wf2h, *wf2l, *wg2h, *wg2l, *w2mh, *w2ml;
    cudaGetSymbolAddress((void**)&grid, g_grid);
    cudaGetSymbolAddress((void**)&h2f,  g_h2f);
    cudaGetSymbolAddress((void**)&cA,   g_convA);
    cudaGetSymbolAddress((void**)&cB,   g_convB);
    cudaGetSymbolAddress((void**)&feat, g_feat);
    cudaGetSymbolAddress((void**)&c1,   g_c1v);
    cudaGetSymbolAddress((void**)&midh, g_midh);
    cudaGetSymbolAddress((void**)&midl, g_midl);
    cudaGetSymbolAddress((void**)&h2bh, g_h2bh);
    cudaGetSymbolAddress((void**)&h2bl, g_h2bl);
    cudaGetSymbolAddress((void**)&wf1h, g_wf1h); cudaGetSymbolAddress((void**)&wf1l, g_wf1l);
    cudaGetSymbolAddress((void**)&wg1h, g_wg1h); cudaGetSymbolAddress((void**)&wg1l, g_wg1l);
    cudaGetSymbolAddress((void**)&wf2h, g_wf2h); cudaGetSymbolAddress((void**)&wf2l, g_wf2l);
    cudaGetSymbolAddress((void**)&wg2h, g_wg2h); cudaGetSymbolAddress((void**)&wg2l, g_wg2l);
    cudaGetSymbolAddress((void**)&w2mh, g_w2mh); cudaGetSymbolAddress((void**)&w2ml, g_w2ml);

    cudaFuncSetAttribute(tgemm<0>, cudaFuncAttributeMaxDynamicSharedMemorySize, TG_SMEM);
    cudaFuncSetAttribute(tgemm<1>, cudaFuncAttributeMaxDynamicSharedMemorySize, TG_SMEM);

    k_gridgen<<<NPIX / 256, 256>>>(grid);
    k_conv<<<768, 256, 448 * 9 * 4>>>(feature, cw1, cb1, cA, 448, 768, 8, 8, 8, 8, 1, 4);
    k_conv<<<768, 256, 256 * 9 * 4>>>(cA, cw2, cb2, cB, 256, 768, 8, 8, 8, 8, 1, 3);
    k_conv<<<768, 256, 384 * 9 * 4>>>(cB, cw3, cb3, cA, 384, 768, 8, 8, 8, 8, 1, 2);
    k_conv<<<768, 256, 256 * 9 * 4>>>(cA, cw4, cb4, cB, 256, 768, 8, 8, 6, 6, 0, 3);
    k_conv<<<128, 256, 768 * 9 * 4>>>(cB, cw5, cb5, feat, 768, 128, 6, 6, 4, 4, 0, 1);
    k_c1<<<128, 256>>>(w1, b1, feat, c1);
    k_wnorm_s<<<4096, 256>>>(m1_vf, m1_gf, wf1h, wf1l, 512);
    k_wnorm_s<<<4096, 256>>>(m1_vg, m1_gg, wg1h, wg1l, 512);
    k_wnorm_s<<<2048, 256>>>(m2_vf, m2_gf, wf2h, wf2l, 256);
    k_wnorm_s<<<2048, 256>>>(m2_vg, m2_gg, wg2h, wg2l, 256);
    k_wsplit<<<512, 256>>>(w2, w2mh, w2ml);

    // mid = lrelu(grid @ w1[:, :32]^T + c1)  -> fp16 hi/lo [65536,1024]
    k_gemm32<0><<<NPIX / 8, 256>>>(grid, w1, 2080, c1, midh, midl, nullptr, 1024, 1024);

    // coupling stack 1 (512-wide halves, in-place on mid pair)
    for (int s = 0; s < 8; s++) {
        tgemm<0><<<dim3(4, 512), 512, TG_SMEM>>>(
            midh + 512, 1024, wf1h + (size_t)s * 262144, wf1l + (size_t)s * 262144, 512,
            m1_bf + s * 512, midh, midl, nullptr, 1024, midh, midl, 1024, 512);
        tgemm<0><<<dim3(4, 512), 512, TG_SMEM>>>(
            midh, 1024, wg1h + (size_t)s * 262144, wg1l + (size_t)s * 262144, 512,
            m1_bg + s * 512, midh + 512, midl + 512, nullptr, 1024, midh + 512, midl + 512, 1024, 512);
    }

    // h2 = lrelu(gridpart(+b2) + mid @ w2[:,32:]^T)
    k_gemm32<1><<<NPIX / 8, 256>>>(grid, w2, 1056, b2, nullptr, nullptr, h2f, 512, 512);
    tgemm<1><<<dim3(4, 512), 512, TG_SMEM>>>(
        midh, 1024, w2mh, w2ml, 1024, nullptr, nullptr, nullptr, h2f, 512,
        h2bh, h2bl, 512, 1024);

    // coupling stack 2 (256-wide halves)
    for (int s = 0; s < 8; s++) {
        tgemm<0><<<dim3(2, 512), 512, TG_SMEM>>>(
            h2bh + 256, 512, wf2h + (size_t)s * 65536, wf2l + (size_t)s * 65536, 256,
            m2_bf + s * 256, h2bh, h2bl, nullptr, 512, h2bh, h2bl, 512, 256);
        tgemm<0><<<dim3(2, 512), 512, TG_SMEM>>>(
            h2bh, 512, wg2h + (size_t)s * 65536, wg2l + (size_t)s * 65536, 256,
            m2_bg + s * 256, h2bh + 256, h2bl + 256, nullptr, 512, h2bh + 256, h2bl + 256, 512, 256);
    }

    k_final<<<NPIX / 8, 256>>>(h2bh, h2bl, w3, b3, out);
}

// round 14
// speedup vs baseline: 1.3375x; 1.1059x over previous
#include <cuda_runtime.h>
#include <cuda_fp16.h>
#include <math.h>
#include <stdint.h>

#define NPIX 65536

// ---------- static scratch ----------
__device__ float g_grid[NPIX * 32];
__device__ float g_h2f[33554432];                     // [65536,512] fp32 partial
__device__ __align__(16) __half g_midh[67108864];     // [65536,1024] hi
__device__ __align__(16) __half g_midl[67108864];     // lo
__device__ __align__(16) __half g_h2bh[33554432];     // [65536,512]
__device__ __align__(16) __half g_h2bl[33554432];
__device__ __align__(16) __half g_wf1h[2097152], g_wf1l[2097152];
__device__ __align__(16) __half g_wg1h[2097152], g_wg1l[2097152];
__device__ __align__(16) __half g_wf2h[524288],  g_wf2l[524288];
__device__ __align__(16) __half g_wg2h[524288],  g_wg2l[524288];
__device__ __align__(16) __half g_w2mh[524288],  g_w2ml[524288];
__device__ float g_convA[768 * 64];
__device__ float g_convB[768 * 64];
__device__ float g_feat[2048];
__device__ float g_c1v[1024];

__device__ __forceinline__ float lrelu(float x) { return x > 0.f ? x : 0.01f * x; }
__device__ __forceinline__ void hf_split(float v, unsigned short& h, unsigned short& l) {
    __half hb = __float2half(v);
    l = __half_as_ushort(__float2half(v - __half2float(hb)));
    h = __half_as_ushort(hb);
}

// ---------- PTX helpers (baseline sm_80 features only) ----------
__device__ __forceinline__ uint32_t smem_u32(const void* p) {
    uint32_t a;
    asm("{ .reg .u64 t; cvta.to.shared.u64 t, %1; cvt.u32.u64 %0, t; }" : "=r"(a) : "l"(p));
    return a;
}
__device__ __forceinline__ void cpa(uint32_t dst, const void* src) {
    asm volatile("cp.async.ca.shared.global [%0], [%1], 16;" :: "r"(dst), "l"(src));
}
#define CP_COMMIT() asm volatile("cp.async.commit_group;" ::: "memory")
template <int N> __device__ __forceinline__ void cp_wait() {
    asm volatile("cp.async.wait_group %0;" :: "n"(N) : "memory");
}
__device__ __forceinline__ void ldmx4(uint32_t* r, uint32_t addr) {
    asm volatile("ldmatrix.sync.aligned.m8n8.x4.shared.b16 {%0,%1,%2,%3}, [%4];"
        : "=r"(r[0]), "=r"(r[1]), "=r"(r[2]), "=r"(r[3]) : "r"(addr));
}
__device__ __forceinline__ void mma16816(float* d, const uint32_t* a, const uint32_t* b) {
    asm volatile(
        "mma.sync.aligned.m16n8k16.row.col.f32.f16.f16.f32 "
        "{%0,%1,%2,%3}, {%4,%5,%6,%7}, {%8,%9}, {%0,%1,%2,%3};"
        : "+f"(d[0]), "+f"(d[1]), "+f"(d[2]), "+f"(d[3])
        : "r"(a[0]), "r"(a[1]), "r"(a[2]), "r"(a[3]), "r"(b[0]), "r"(b[1]));
}

// ---------- grid features ----------
__global__ void k_gridgen(float* __restrict__ g) {
    int p = blockIdx.x * blockDim.x + threadIdx.x;
    float fi = (float)((p >> 8) - 128);
    float fj = (float)((p & 255) - 128);
    float* row = g + (size_t)p * 32;
#pragma unroll
    for (int k = 0; k < 16; k++) {
        float s = exp2f(0.5f * k - 8.0f);
        row[2 * k]     = sinpif(fi * s);
        row[2 * k + 1] = sinpif(fj * s);
    }
}

// ---------- 3x3 grouped conv, 256 thr, 4-way ci slices ----------
__global__ void k_conv(const float* __restrict__ in, const float* __restrict__ w,
                       const float* __restrict__ b, float* __restrict__ out,
                       int Cipg, int Cout, int Hin, int Win, int Hout, int Wout,
                       int pad, int groups) {
    extern __shared__ float ws[];
    __shared__ float red[4][64];
    int o = blockIdx.x;
    int opg = Cout / groups;
    const float* inb = in + (size_t)(o / opg) * Cipg * Hin * Win;
    const float* wb = w + (size_t)o * Cipg * 9;
    int nw = Cipg * 9;
    for (int i = threadIdx.x; i < nw; i += blockDim.x) ws[i] = wb[i];
    __syncthreads();
    int np = Hout * Wout;
    int sl = threadIdx.x >> 6, p = threadIdx.x & 63;
    int cps = Cipg >> 2;
    float acc = 0.f;
    if (p < np) {
        int y = p / Wout, x = p % Wout;
        for (int ci = sl * cps; ci < (sl + 1) * cps; ci++) {
            const float* ip = inb + (size_t)ci * Hin * Win;
            const float* wp = ws + ci * 9;
#pragma unroll
            for (int ky = 0; ky < 3; ky++) {
                int iy = y + ky - pad;
                if ((unsigned)iy < (unsigned)Hin) {
#pragma unroll
                    for (int kx = 0; kx < 3; kx++) {
                        int ix = x + kx - pad;
                        if ((unsigned)ix < (unsigned)Win)
                            acc += ip[iy * Win + ix] * wp[ky * 3 + kx];
                    }
                }
            }
        }
    }
    red[sl][p] = acc;
    __syncthreads();
    if (sl == 0 && p < np)
        out[(size_t)o * np + p] = lrelu(red[0][p] + red[1][p] + red[2][p] + red[3][p] + b[o]);
}

// ---------- weight norm + fp16 split ----------
__global__ void k_wnorm_s(const float* __restrict__ v, const float* __restrict__ g,
                          __half* __restrict__ oh, __half* __restrict__ ol, int R) {
    int row = blockIdx.x;
    const float* vr = v + (size_t)row * R;
    float s = 0.f;
    for (int k = threadIdx.x; k < R; k += 256) { float x = vr[k]; s += x * x; }
    __shared__ float red[256];
    red[threadIdx.x] = s;
    __syncthreads();
    for (int st = 128; st > 0; st >>= 1) {
        if (threadIdx.x < st) red[threadIdx.x] += red[threadIdx.x + st];
        __syncthreads();
    }
    float sc = g[row] / sqrtf(red[0]);
    for (int k = threadIdx.x; k < R; k += 256) {
        unsigned short h, l;
        hf_split(vr[k] * sc, h, l);
        oh[(size_t)row * R + k] = __ushort_as_half(h);
        ol[(size_t)row * R + k] = __ushort_as_half(l);
    }
}

// ---------- w2[:,32:] split ----------
__global__ void k_wsplit(const float* __restrict__ w2, __half* __restrict__ oh,
                         __half* __restrict__ ol) {
    int r = blockIdx.x;
    for (int k = threadIdx.x; k < 1024; k += 256) {
        unsigned short h, l;
        hf_split(w2[(size_t)r * 1056 + 32 + k], h, l);
        oh[(size_t)r * 1024 + k] = __ushort_as_half(h);
        ol[(size_t)r * 1024 + k] = __ushort_as_half(l);
    }
}

// ---------- c1 = w1[:,32:] @ feat + b1 ----------
__global__ void k_c1(const float* __restrict__ w1, const float* __restrict__ b1,
                     const float* __restrict__ feat, float* __restrict__ c1) {
    int o = blockIdx.x * 8 + (threadIdx.x >> 5);
    int lane = threadIdx.x & 31;
    const float* wr = w1 + (size_t)o * 2080 + 32;
    float s = 0.f;
    for (int k = lane; k < 2048; k += 32) s += wr[k] * feat[k];
#pragma unroll
    for (int off = 16; off; off >>= 1) s += __shfl_xor_sync(0xffffffffu, s, off);
    if (lane == 0) c1[o] = s + b1[o];
}

// ---------- K=32 fp32 GEMM: MODE0 -> lrelu + fp16 split; MODE1 -> fp32 out ----------
template <int MODE>
__global__ void __launch_bounds__(256) k_gemm32(
    const float* __restrict__ A, const float* __restrict__ W, int ldw,
    const float* __restrict__ bias,
    __half* __restrict__ oh, __half* __restrict__ ol,
    float* __restrict__ of, int ldc, int O) {
    __shared__ float As[8][32];
    int r0 = blockIdx.x * 8;
    As[threadIdx.x >> 5][threadIdx.x & 31] = A[(size_t)(r0 + (threadIdx.x >> 5)) * 32 + (threadIdx.x & 31)];
    __syncthreads();
    int wrow = threadIdx.x >> 5, lane = threadIdx.x & 31;
    float a[32];
#pragma unroll
    for (int k = 0; k < 32; k++) a[k] = As[wrow][k];
    size_t row = r0 + wrow;
    for (int cb = 0; cb < O; cb += 256) {
        float v[8];
#pragma unroll
        for (int j = 0; j < 8; j++) {
            int col = cb + lane * 8 + j;
            const float4* wr = (const float4*)(W + (size_t)col * ldw);
            float s = 0.f;
#pragma unroll
            for (int q = 0; q < 8; q++) {
                float4 wv = wr[q];
                s += a[q*4] * wv.x + a[q*4+1] * wv.y + a[q*4+2] * wv.z + a[q*4+3] * wv.w;
            }
            v[j] = s + bias[col];
            if (MODE == 0) v[j] = lrelu(v[j]);
        }
        if (MODE == 0) {
            unsigned short hh[8], ll[8];
#pragma unroll
            for (int j = 0; j < 8; j++) hf_split(v[j], hh[j], ll[j]);
            *(uint4*)(oh + row * ldc + cb + lane * 8) = *(uint4*)hh;
            *(uint4*)(ol + row * ldc + cb + lane * 8) = *(uint4*)ll;
        } else {
            float* dst = of + row * ldc + cb + lane * 8;
            *(float4*)dst = *(float4*)v;
            *(float4*)(dst + 4) = *(float4*)(v + 4);
        }
    }
}

// ---------- mma.sync fp16x2 GEMM: C = epi(Ah[65536,K] @ (Wh+Wl)[O,K]^T) ----------
// A consumed as fp16 hi only (Al carried in residual, not MMA'd). 2 MMAs/cell.
// MODE 0: out = (Rh+Rl) + lrelu(acc + bias)   -> fp16 hi/lo (coupling, in-place safe)
// MODE 1: out = lrelu(acc + Rf)               -> fp16 hi/lo (concat pass; Rf has bias)
// CTA tile 128x128, BK=64, 512 threads, warp tile 32x32, 2-stage double buffer.
#define TPITCH 144u      // bytes per padded 64-elt fp16 row
#define TBYTES 18432u    // one 128-row tile
#define SBYTES 55296u    // 3 tiles (Ah, Wh, Wl) = one stage
template <int MODE>
__global__ void __launch_bounds__(512, 1) tgemm(
    const __half* __restrict__ Ah, int lda,
    const __half* __restrict__ Wh, const __half* __restrict__ Wl, int ldw,
    const float* __restrict__ bias,
    const __half* __restrict__ Rh, const __half* __restrict__ Rl,
    const float* __restrict__ Rf, int ldr,
    __half* __restrict__ Coh, __half* __restrict__ Col, int ldc, int K) {
    extern __shared__ char smem[];
    uint32_t sb = smem_u32(smem);
    int tid = threadIdx.x;
    int lane = tid & 31, wid = tid >> 5;
    int wm = wid & 3, wn = wid >> 2;     // 4 x 4 warp grid, 32x32 tiles
    int row0 = blockIdx.y * 128, col0 = blockIdx.x * 128;

    float acc[2][4][4];
#pragma unroll
    for (int i = 0; i < 2; i++)
#pragma unroll
        for (int j = 0; j < 4; j++)
#pragma unroll
            for (int q = 0; q < 4; q++) acc[i][j][q] = 0.f;

    // ldmatrix lane->address precompute
    int arow = lane & 15, acol = (lane & 16) >> 1;                 // A frags 16x16
    int brow = (lane & 7) + ((lane & 16) >> 1), bcol = lane & 8;   // B frags 16x16

    // cp.async: per tile 128 rows x 8 16B-chunks = 1024 units; thread t does t, t+512
    int r0c = tid >> 3, q0c = tid & 7;
    uint32_t so0 = (uint32_t)r0c * TPITCH + (uint32_t)q0c * 16u;
    uint32_t so1 = (uint32_t)(r0c + 64) * TPITCH + (uint32_t)q0c * 16u;

    int nch = K >> 6;
    auto issue = [&](int c) {
        uint32_t base = sb + (uint32_t)(c & 1) * SBYTES;
        int kc = c << 6;
        size_t ga0 = (size_t)(row0 + r0c) * lda + kc + q0c * 8;
        size_t ga1 = (size_t)(row0 + r0c + 64) * lda + kc + q0c * 8;
        size_t gw0 = (size_t)(col0 + r0c) * ldw + kc + q0c * 8;
        size_t gw1 = (size_t)(col0 + r0c + 64) * ldw + kc + q0c * 8;
        cpa(base + so0,              Ah + ga0);
        cpa(base + so1,              Ah + ga1);
        cpa(base + TBYTES + so0,     Wh + gw0);
        cpa(base + TBYTES + so1,     Wh + gw1);
        cpa(base + 2 * TBYTES + so0, Wl + gw0);
        cpa(base + 2 * TBYTES + so1, Wl + gw1);
        CP_COMMIT();
    };

    issue(0);
    for (int c = 0; c < nch; c++) {
        if (c + 1 < nch) { issue(c + 1); cp_wait<1>(); } else { cp_wait<0>(); }
        __syncthreads();
        uint32_t base = sb + (uint32_t)(c & 1) * SBYTES;
#pragma unroll
        for (int kk = 0; kk < 4; kk++) {
            uint32_t ah[2][4];
#pragma unroll
            for (int mi = 0; mi < 2; mi++) {
                uint32_t off = (uint32_t)(wm * 32 + mi * 16 + arow) * TPITCH + (uint32_t)(kk * 16 + acol) * 2u;
                ldmx4(ah[mi], base + off);
            }
            uint32_t bh[2][4], bv[2][4];
#pragma unroll
            for (int pi = 0; pi < 2; pi++) {
                uint32_t off = (uint32_t)(wn * 32 + pi * 16 + brow) * TPITCH + (uint32_t)(kk * 16 + bcol) * 2u;
                ldmx4(bh[pi], base + TBYTES + off);
                ldmx4(bv[pi], base + 2 * TBYTES + off);
            }
#pragma unroll
            for (int mi = 0; mi < 2; mi++)
#pragma unroll
                for (int ni = 0; ni < 4; ni++) {
                    const uint32_t* bhp = &bh[ni >> 1][(ni & 1) << 1];
                    const uint32_t* bvp = &bv[ni >> 1][(ni & 1) << 1];
                    mma16816(acc[mi][ni], ah[mi], bhp);   // Ah*Wh
                    mma16816(acc[mi][ni], ah[mi], bvp);   // Ah*Wl
                }
        }
        __syncthreads();
    }

    // epilogue
    int gid = lane >> 2, tig = lane & 3;
#pragma unroll
    for (int mi = 0; mi < 2; mi++) {
#pragma unroll
        for (int ni = 0; ni < 4; ni++) {
            int col = col0 + wn * 32 + ni * 8 + tig * 2;
#pragma unroll
            for (int h = 0; h < 2; h++) {
                size_t r = (size_t)(row0 + wm * 32 + mi * 16 + gid + h * 8);
                float v0 = acc[mi][ni][h * 2], v1 = acc[mi][ni][h * 2 + 1];
                if (MODE == 0) {
                    float2 bb = *(const float2*)(bias + col);
                    v0 = lrelu(v0 + bb.x);
                    v1 = lrelu(v1 + bb.y);
                    __half2 hh = *(const __half2*)(Rh + r * ldr + col);
                    __half2 ll = *(const __half2*)(Rl + r * ldr + col);
                    v0 += __half2float(hh.x) + __half2float(ll.x);
                    v1 += __half2float(hh.y) + __half2float(ll.y);
                } else {
                    float2 rf = *(const float2*)(Rf + r * ldr + col);
                    v0 = lrelu(v0 + rf.x);
                    v1 = lrelu(v1 + rf.y);
                }
                unsigned short h0, l0, h1, l1;
                hf_split(v0, h0, l0);
                hf_split(v1, h1, l1);
                *(uint32_t*)(Coh + r * ldc + col) = (uint32_t)h0 | ((uint32_t)h1 << 16);
                *(uint32_t*)(Col + r * ldc + col) = (uint32_t)l0 | ((uint32_t)l1 << 16);
            }
        }
    }
}

// ---------- final rgb head ----------
__global__ void k_final(const __half* __restrict__ hh, const __half* __restrict__ hl,
                        const float* __restrict__ w3, const float* __restrict__ b3,
                        float* __restrict__ out) {
    int gw = (blockIdx.x * blockDim.x + threadIdx.x) >> 5;
    int lane = threadIdx.x & 31;
    const __half* rh = hh + (size_t)gw * 512;
    const __half* rl = hl + (size_t)gw * 512;
    float s0 = 0.f, s1 = 0.f, s2 = 0.f;
    for (int k = lane; k < 512; k += 32) {
        float h = __half2float(rh[k]) + __half2float(rl[k]);
        s0 += h * w3[k];
        s1 += h * w3[512 + k];
        s2 += h * w3[1024 + k];
    }
#pragma unroll
    for (int off = 16; off; off >>= 1) {
        s0 += __shfl_xor_sync(0xffffffffu, s0, off);
        s1 += __shfl_xor_sync(0xffffffffu, s1, off);
        s2 += __shfl_xor_sync(0xffffffffu, s2, off);
    }
    if (lane == 0) {
        out[gw]            = 1.1f / (1.f + expf(-(s0 + b3[0]))) - 0.05f;
        out[NPIX + gw]     = 1.1f / (1.f + expf(-(s1 + b3[1]))) - 0.05f;
        out[2 * NPIX + gw] = 1.1f / (1.f + expf(-(s2 + b3[2]))) - 0.05f;
    }
}

// ---------- host ----------
#define TG_SMEM 110592
extern "C" void kernel_launch(void* const* d_in, const int* in_sizes, int n_in,
                              void* d_out, int out_size) {
    const float* feature = (const float*)d_in[0];
    const float* cw1 = (const float*)d_in[1];  const float* cb1 = (const float*)d_in[2];
    const float* cw2 = (const float*)d_in[3];  const float* cb2 = (const float*)d_in[4];
    const float* cw3 = (const float*)d_in[5];  const float* cb3 = (const float*)d_in[6];
    const float* cw4 = (const float*)d_in[7];  const float* cb4 = (const float*)d_in[8];
    const float* cw5 = (const float*)d_in[9];  const float* cb5 = (const float*)d_in[10];
    const float* w1  = (const float*)d_in[11]; const float* b1  = (const float*)d_in[12];
    const float* m1_vf = (const float*)d_in[13]; const float* m1_gf = (const float*)d_in[14]; const float* m1_bf = (const float*)d_in[15];
    const float* m1_vg = (const float*)d_in[16]; const float* m1_gg = (const float*)d_in[17]; const float* m1_bg = (const float*)d_in[18];
    const float* w2  = (const float*)d_in[19]; const float* b2  = (const float*)d_in[20];
    const float* m2_vf = (const float*)d_in[21]; const float* m2_gf = (const float*)d_in[22]; const float* m2_bf = (const float*)d_in[23];
    const float* m2_vg = (const float*)d_in[24]; const float* m2_gg = (const float*)d_in[25]; const float* m2_bg = (const float*)d_in[26];
    const float* w3  = (const float*)d_in[27]; const float* b3  = (const float*)d_in[28];
    float* out = (float*)d_out;

    float *grid, *h2f, *cA, *cB, *feat, *c1;
    __half *midh, *midl, *h2bh, *h2bl;
    __half *wf1h, *wf1l, *wg1h, *wg1l, *wf2h, *wf2l, *wg2h, *wg2l, *w2mh, *w2ml;
    cudaGetSymbolAddress((void**)&grid, g_grid);
    cudaGetSymbolAddress((void**)&h2f,  g_h2f);
    cudaGetSymbolAddress((void**)&cA,   g_convA);
    cudaGetSymbolAddress((void**)&cB,   g_convB);
    cudaGetSymbolAddress((void**)&feat, g_feat);
    cudaGetSymbolAddress((void**)&c1,   g_c1v);
    cudaGetSymbolAddress((void**)&midh, g_midh);
    cudaGetSymbolAddress((void**)&midl, g_midl);
    cudaGetSymbolAddress((void**)&h2bh, g_h2bh);
    cudaGetSymbolAddress((void**)&h2bl, g_h2bl);
    cudaGetSymbolAddress((void**)&wf1h, g_wf1h); cudaGetSymbolAddress((void**)&wf1l, g_wf1l);
    cudaGetSymbolAddress((void**)&wg1h, g_wg1h); cudaGetSymbolAddress((void**)&wg1l, g_wg1l);
    cudaGetSymbolAddress((void**)&wf2h, g_wf2h); cudaGetSymbolAddress((void**)&wf2l, g_wf2l);
    cudaGetSymbolAddress((void**)&wg2h, g_wg2h); cudaGetSymbolAddress((void**)&wg2l, g_wg2l);
    cudaGetSymbolAddress((void**)&w2mh, g_w2mh); cudaGetSymbolAddress((void**)&w2ml, g_w2ml);

    cudaFuncSetAttribute(tgemm<0>, cudaFuncAttributeMaxDynamicSharedMemorySize, TG_SMEM);
    cudaFuncSetAttribute(tgemm<1>, cudaFuncAttributeMaxDynamicSharedMemorySize, TG_SMEM);

    k_gridgen<<<NPIX / 256, 256>>>(grid);
    k_conv<<<768, 256, 448 * 9 * 4>>>(feature, cw1, cb1, cA, 448, 768, 8, 8, 8, 8, 1, 4);
    k_conv<<<768, 256, 256 * 9 * 4>>>(cA, cw2, cb2, cB, 256, 768, 8, 8, 8, 8, 1, 3);
    k_conv<<<768, 256, 384 * 9 * 4>>>(cB, cw3, cb3, cA, 384, 768, 8, 8, 8, 8, 1, 2);
    k_conv<<<768, 256, 256 * 9 * 4>>>(cA, cw4, cb4, cB, 256, 768, 8, 8, 6, 6, 0, 3);
    k_conv<<<128, 256, 768 * 9 * 4>>>(cB, cw5, cb5, feat, 768, 128, 6, 6, 4, 4, 0, 1);
    k_c1<<<128, 256>>>(w1, b1, feat, c1);
    k_wnorm_s<<<4096, 256>>>(m1_vf, m1_gf, wf1h, wf1l, 512);
    k_wnorm_s<<<4096, 256>>>(m1_vg, m1_gg, wg1h, wg1l, 512);
    k_wnorm_s<<<2048, 256>>>(m2_vf, m2_gf, wf2h, wf2l, 256);
    k_wnorm_s<<<2048, 256>>>(m2_vg, m2_gg, wg2h, wg2l, 256);
    k_wsplit<<<512, 256>>>(w2, w2mh, w2ml);

    // mid = lrelu(grid @ w1[:, :32]^T + c1)  -> fp16 hi/lo [65536,1024]
    k_gemm32<0><<<NPIX / 8, 256>>>(grid, w1, 2080, c1, midh, midl, nullptr, 1024, 1024);

    // coupling stack 1 (512-wide halves, in-place on mid pair)
    for (int s = 0; s < 8; s++) {
        tgemm<0><<<dim3(4, 512), 512, TG_SMEM>>>(
            midh + 512, 1024, wf1h + (size_t)s * 262144, wf1l + (size_t)s * 262144, 512,
            m1_bf + s * 512, midh, midl, nullptr, 1024, midh, midl, 1024, 512);
        tgemm<0><<<dim3(4, 512), 512, TG_SMEM>>>(
            midh, 1024, wg1h + (size_t)s * 262144, wg1l + (size_t)s * 262144, 512,
            m1_bg + s * 512, midh + 512, midl + 512, nullptr, 1024, midh + 512, midl + 512, 1024, 512);
    }

    // h2 = lrelu(gridpart(+b2) + mid @ w2[:,32:]^T)
    k_gemm32<1><<<NPIX / 8, 256>>>(grid, w2, 1056, b2, nullptr, nullptr, h2f, 512, 512);
    tgemm<1><<<dim3(4, 512), 512, TG_SMEM>>>(
        midh, 1024, w2mh, w2ml, 1024, nullptr, nullptr, nullptr, h2f, 512,
        h2bh, h2bl, 512, 1024);

    // coupling stack 2 (256-wide halves)
    for (int s = 0; s < 8; s++) {
        tgemm<0><<<dim3(2, 512), 512, TG_SMEM>>>(
            h2bh + 256, 512, wf2h + (size_t)s * 65536, wf2l + (size_t)s * 65536, 256,
            m2_bf + s * 256, h2bh, h2bl, nullptr, 512, h2bh, h2bl, 512, 256);
        tgemm<0><<<dim3(2, 512), 512, TG_SMEM>>>(
            h2bh, 512, wg2h + (size_t)s * 65536, wg2l + (size_t)s * 65536, 256,
            m2_bg + s * 256, h2bh + 256, h2bl + 256, nullptr, 512, h2bh + 256, h2bl + 256, 512, 256);
    }

    k_final<<<NPIX / 8, 256>>>(h2bh, h2bl, w3, b3, out);
}